// round 14
// baseline (speedup 1.0000x reference)
#include <cuda_runtime.h>
#include <cuda_fp16.h>
#include <stdint.h>

// ---------------------------------------------------------------------------
// Problem constants
// ---------------------------------------------------------------------------
#define Gc 64
#define Nc 256
#define Fc 20
#define Hc 32
#define Kc 5
#define NSc 100
#define ZP 40      // Z/h fp16 smem pitch (elements)
#define TP 34      // Tb fp32 smem pitch (elements)
#define NT 512

static const size_t PROB_ELEMS = (size_t)Gc * Nc * Nc * Kc;            // 20971520
static const size_t LA_OFF     = PROB_ELEMS;
static const size_t ZMU_OFF    = LA_OFF + (size_t)Gc * Kc;
static const size_t LOSS_OFF   = ZMU_OFF + (size_t)Gc * Nc * Hc;

// ---------------------------------------------------------------------------
// Scratch (device globals; no runtime allocation allowed)
// ---------------------------------------------------------------------------
__device__ float        g_ha[(size_t)Gc * Nc * Hc];
__device__ unsigned int g_uthr[(size_t)Kc * Gc * Nc * Nc];  // min b9 s.t. edge
__device__ float        g_la[Gc * Kc];
__device__ float        g_partial[NSc * Gc];

// ---------------------------------------------------------------------------
// threefry2x32 (bit-exact JAX, partitionable mode); adds on FMA pipe via IMAD
// ---------------------------------------------------------------------------
struct U2 { unsigned int x, y; };

__device__ __forceinline__ unsigned int uadd_fma(unsigned int a, unsigned int b,
                                                 unsigned int one)
{
    unsigned int d;
    asm("mad.lo.u32 %0, %1, %2, %3;" : "=r"(d) : "r"(a), "r"(one), "r"(b));
    return d;
}

__device__ __forceinline__ unsigned int rotl32(unsigned int v, int r) {
    return (v << r) | (v >> (32 - r));
}

__device__ __forceinline__ U2 threefry(unsigned int k0, unsigned int k1,
                                       unsigned int x0, unsigned int x1,
                                       unsigned int onev)
{
    unsigned int k2 = k0 ^ k1 ^ 0x1BD11BDAu;
    x0 = uadd_fma(x0, k0, onev); x1 = uadd_fma(x1, k1, onev);
#define TFR(r) { x0 = uadd_fma(x0, x1, onev); x1 = rotl32(x1, r) ^ x0; }
    TFR(13) TFR(15) TFR(26) TFR(6)
    x0 = uadd_fma(x0, k1, onev); x1 = uadd_fma(x1, k2 + 1u, onev);
    TFR(17) TFR(29) TFR(16) TFR(24)
    x0 = uadd_fma(x0, k2, onev); x1 = uadd_fma(x1, k0 + 2u, onev);
    TFR(13) TFR(15) TFR(26) TFR(6)
    x0 = uadd_fma(x0, k0, onev); x1 = uadd_fma(x1, k1 + 3u, onev);
    TFR(17) TFR(29) TFR(16) TFR(24)
    x0 = uadd_fma(x0, k1, onev); x1 = uadd_fma(x1, k2 + 4u, onev);
    TFR(13) TFR(15) TFR(26) TFR(6)
    x0 = uadd_fma(x0, k2, onev); x1 = uadd_fma(x1, k0 + 5u, onev);
#undef TFR
    U2 r; r.x = x0; r.y = x1; return r;
}

__device__ __forceinline__ unsigned int rbits(unsigned int k0, unsigned int k1,
                                              unsigned int idx, unsigned int onev)
{
    U2 r = threefry(k0, k1, 0u, idx, onev);
    return r.x ^ r.y;
}

__device__ __forceinline__ float bits_to_f01(unsigned int b)
{
    return __uint_as_float((b >> 9) | 0x3f800000u) - 1.0f;
}

// XLA fp32 ErfInv (Giles polynomial); w via fast log
__device__ __forceinline__ float erfinv32(float x)
{
    float w = -__logf(1.0f - x * x);
    float p;
    if (w < 5.0f) {
        w = w - 2.5f;
        p = 2.81022636e-08f;
        p = fmaf(p, w, 3.43273939e-07f);
        p = fmaf(p, w, -3.5233877e-06f);
        p = fmaf(p, w, -4.39150654e-06f);
        p = fmaf(p, w, 0.00021858087f);
        p = fmaf(p, w, -0.00125372503f);
        p = fmaf(p, w, -0.00417768164f);
        p = fmaf(p, w, 0.246640727f);
        p = fmaf(p, w, 1.50140941f);
    } else {
        w = sqrtf(w) - 3.0f;
        p = -0.000200214257f;
        p = fmaf(p, w, 0.000100950558f);
        p = fmaf(p, w, 0.00134934322f);
        p = fmaf(p, w, -0.00367342844f);
        p = fmaf(p, w, 0.00573950773f);
        p = fmaf(p, w, -0.0076224613f);
        p = fmaf(p, w, 0.00943887047f);
        p = fmaf(p, w, 1.00167406f);
        p = fmaf(p, w, 2.83297682f);
    }
    return p * x;
}

__device__ __forceinline__ unsigned int smem_u32(const void* p)
{
    unsigned int a;
    asm("{ .reg .u64 t; cvta.to.shared.u64 t, %1; cvt.u32.u64 %0, t; }"
        : "=r"(a) : "l"(p));
    return a;
}

// 32x32 bit-matrix transpose, one row per lane (LSB = column 0).
__device__ __forceinline__ unsigned int bit_transpose32(unsigned int x, int lane)
{
#pragma unroll
    for (int j = 16; j >= 1; j >>= 1) {
        unsigned int mh = (j == 16) ? 0xFFFF0000u :
                          (j == 8)  ? 0xFF00FF00u :
                          (j == 4)  ? 0xF0F0F0F0u :
                          (j == 2)  ? 0xCCCCCCCCu : 0xAAAAAAAAu;
        unsigned int y = __shfl_xor_sync(0xffffffffu, x, j);
        if (lane & j) x = (x & mh) | ((y >> j) & ~mh);
        else          x = (x & ~mh) | ((y << j) & mh);
    }
    return x;
}

// ---------------------------------------------------------------------------
// Encoders: Z_mu, ha, and logit_alpha (fused)
// ---------------------------------------------------------------------------
__global__ void encode_kernel(const float* __restrict__ X,
                              const float* __restrict__ Wz1, const float* __restrict__ bz1,
                              const float* __restrict__ Wz2, const float* __restrict__ bz2,
                              const float* __restrict__ Wa1, const float* __restrict__ ba1,
                              const float* __restrict__ Walpha, const float* __restrict__ balpha,
                              float* __restrict__ zmu_out, float* __restrict__ la_out)
{
    __shared__ float sWz1[Fc * Hc], sbz1[Hc], sWz2[Hc * Hc], sbz2[Hc];
    __shared__ float sWa1[Fc * Hc], sba1[Hc];
    __shared__ float red[256];
    int t = threadIdx.x, g = blockIdx.x;
    for (int i = t; i < Fc * Hc; i += 256) { sWz1[i] = Wz1[i]; sWa1[i] = Wa1[i]; }
    for (int i = t; i < Hc * Hc; i += 256) sWz2[i] = Wz2[i];
    if (t < Hc) { sbz1[t] = bz1[t]; sbz2[t] = bz2[t]; sba1[t] = ba1[t]; }
    __syncthreads();

    float xr[Fc];
    const float* xp = X + ((size_t)g * Nc + t) * Fc;
#pragma unroll
    for (int f = 0; f < Fc; ++f) xr[f] = xp[f];

    float hz[Hc];
#pragma unroll
    for (int h = 0; h < Hc; ++h) {
        float a = sbz1[h];
#pragma unroll
        for (int f = 0; f < Fc; ++f) a = fmaf(xr[f], sWz1[f * Hc + h], a);
        hz[h] = fmaxf(a, 0.0f);
    }
    float* zo = zmu_out + ((size_t)g * Nc + t) * Hc;
#pragma unroll
    for (int h = 0; h < Hc; ++h) {
        float a = sbz2[h];
#pragma unroll
        for (int q = 0; q < Hc; ++q) a = fmaf(hz[q], sWz2[q * Hc + h], a);
        zo[h] = a;
    }
    float* hao = g_ha + ((size_t)g * Nc + t) * Hc;
#pragma unroll
    for (int h = 0; h < Hc; ++h) {
        float a = sba1[h];
#pragma unroll
        for (int f = 0; f < Fc; ++f) a = fmaf(xr[f], sWa1[f * Hc + h], a);
        hao[h] = fmaxf(a, 0.0f);
    }
    __syncthreads();

    int h = t & 31, grp = t >> 5;
    float s = 0.0f;
    for (int n = grp; n < Nc; n += 8) s += g_ha[((size_t)g * Nc + n) * Hc + h];
    red[t] = s;
    __syncthreads();
    if (grp == 0) {
        float m = red[h] + red[32 + h] + red[64 + h] + red[96 + h] +
                  red[128 + h] + red[160 + h] + red[192 + h] + red[224 + h];
        red[h] = m * (1.0f / (float)Nc);
    }
    __syncthreads();
    if (t < Kc) {
        float a = balpha[t];
#pragma unroll
        for (int hh = 0; hh < Hc; ++hh) a = fmaf(red[hh], Walpha[hh * Kc + t], a);
        la_out[g * Kc + t] = a;
        g_la[g * Kc + t] = a;
    }
}

// ---------------------------------------------------------------------------
// theta: prob_theta (output) + exact integer thresholds (scratch)
// b9min = smallest b9 in [0, 2^23) with fmax(loA, fmaf(b9*2^-23, scA, loA)) > thv
// (monotone in b9; double-precision candidate is within 1 step; verify +-4)
// ---------------------------------------------------------------------------
__global__ void theta_kernel(const float* __restrict__ Wtheta,
                             float* __restrict__ prob_out)
{
    extern __shared__ float sm[];
    float* ha = sm;                    // 256*33
    float* B  = sm + Nc * 33;          // 64*33
    float* Th = sm + Nc * 33 + 64 * 33;
    int bid = blockIdx.x;
    int g = bid / (Kc * 4);
    int rem = bid % (Kc * 4);
    int k = rem >> 2;
    int i0 = (rem & 3) * 64;
    int t = threadIdx.x;

    const float loA = 1e-6f;
    const float scA = (1.0f - 1e-6f) - 1e-6f;
    const double inv_scA = 1.0 / (double)scA;

    for (int e = t; e < Nc * Hc; e += 256) {
        int i = e >> 5, h = e & 31;
        ha[i * 33 + h] = g_ha[((size_t)g * Nc + i) * Hc + h];
    }
    for (int e = t; e < Hc * Hc; e += 256) Th[e] = Wtheta[(size_t)e * Kc + k];
    __syncthreads();

    for (int e = t; e < 64 * Hc; e += 256) {
        int i = e >> 5, f = e & 31;
        float a = 0.0f;
#pragma unroll
        for (int h = 0; h < Hc; ++h) a = fmaf(ha[(i0 + i) * 33 + h], Th[h * Hc + f], a);
        B[i * 33 + f] = a;
    }
    __syncthreads();

    int lane = t & 31, w = t >> 5;
    for (int ii = 0; ii < 8; ++ii) {
        int il = w * 8 + ii;
        int i  = i0 + il;
        float br[Hc];
#pragma unroll
        for (int f = 0; f < Hc; ++f) br[f] = B[il * 33 + f];
        for (int jh = 0; jh < 8; ++jh) {
            int j = jh * 32 + lane;
            float a = 0.0f;
#pragma unroll
            for (int f = 0; f < Hc; ++f) a = fmaf(br[f], ha[j * 33 + f], a);
            float e    = __expf(-a);
            float prob = __fdividef(1.0f, 1.0f + e);
            float thv  = e * prob;                     // sigmoid(-a)
            prob_out[(((size_t)g * Nc + i) * Nc + j) * Kc + k] = (i == j) ? 0.0f : prob;

            // exact integer threshold
            double td = ((double)thv - (double)loA) * inv_scA * 8388608.0;
            int cand = (int)floor(td);
            int lo = cand - 4; if (lo < 0) lo = 0;
            int hi = cand + 4; if (hi > 8388607) hi = 8388607;
            unsigned int b9min = 8388608u;   // never
            for (int b9 = lo; b9 <= hi; ++b9) {
                float f = __uint_as_float((unsigned int)b9 | 0x3f800000u) - 1.0f;
                float u = fmaxf(loA, fmaf(f, scA, loA));
                if (u > thv) { b9min = (unsigned int)b9; break; }
            }
            g_uthr[(((size_t)k * Gc + g) * Nc + i) * Nc + j] = b9min;
        }
    }
}

// ---------------------------------------------------------------------------
// MMA helpers (base PTX ISA)
// ---------------------------------------------------------------------------
#define LDSM4T(r0, r1, r2, r3, addr)                                          \
    asm volatile("ldmatrix.sync.aligned.m8n8.x4.trans.shared.b16 "            \
                 "{%0,%1,%2,%3}, [%4];"                                       \
                 : "=r"(r0), "=r"(r1), "=r"(r2), "=r"(r3) : "r"(addr))

#define MMA16816F(d, a, b0_, b1_)                                             \
    asm volatile("mma.sync.aligned.m16n8k16.row.col.f32.f16.f16.f32 "         \
                 "{%0,%1,%2,%3}, {%4,%5,%6,%7}, {%8,%9}, {%0,%1,%2,%3};"      \
                 : "+f"((d)[0]), "+f"((d)[1]), "+f"((d)[2]), "+f"((d)[3])     \
                 : "r"((a)[0]), "r"((a)[1]), "r"((a)[2]), "r"((a)[3]),        \
                   "r"(b0_), "r"(b1_))

__device__ __forceinline__ unsigned int bits2h(unsigned int b)
{
    return (b & 1u) * 0x3C00u + ((b >> 1) & 1u) * 0x3C000000u;
}

__device__ __forceinline__ void amul_mma(unsigned int zh_b,
                                         const unsigned int* __restrict__ Ab,
                                         float* __restrict__ Tb, int t)
{
    const int l = t & 31, w = t >> 5;
    const int m0 = w * 16;
    const int g  = l >> 2;
    const int qs = (l & 3) * 2;
    const int krow = l & 15;
    const int kcol = (l >> 4) * 8;

    float acc[4][4];
#pragma unroll
    for (int nt = 0; nt < 4; ++nt)
#pragma unroll
        for (int r = 0; r < 4; ++r) acc[nt][r] = 0.0f;

#pragma unroll 4
    for (int kc = 0; kc < 16; ++kc) {
        const int sh = ((kc & 1) << 4) + qs;
        unsigned int a[4];
        {
            unsigned int wlo = Ab[(m0 + g) * 8 + (kc >> 1)];
            unsigned int whi = Ab[(m0 + 8 + g) * 8 + (kc >> 1)];
            unsigned int bl = wlo >> sh;
            unsigned int bh = whi >> sh;
            a[0] = bits2h(bl);
            a[1] = bits2h(bh);
            a[2] = bits2h(bl >> 8);
            a[3] = bits2h(bh >> 8);
        }
#pragma unroll
        for (int ng = 0; ng < 2; ++ng) {
            unsigned int off = (unsigned int)(((kc * 16 + krow) * ZP
                                               + ng * 16 + kcol) * 2);
            unsigned int h0, h1, h2, h3;
            LDSM4T(h0, h1, h2, h3, zh_b + off);
            MMA16816F(acc[ng * 2 + 0], a, h0, h1);
            MMA16816F(acc[ng * 2 + 1], a, h2, h3);
        }
    }

#pragma unroll
    for (int nt = 0; nt < 4; ++nt) {
        int r0 = m0 + g;
        int c  = nt * 8 + qs;
        *(float2*)&Tb[r0 * TP + c]       = make_float2(acc[nt][0], acc[nt][1]);
        *(float2*)&Tb[(r0 + 8) * TP + c] = make_float2(acc[nt][2], acc[nt][3]);
    }
}

// ---------------------------------------------------------------------------
// Fused per-(sample, graph) kernel, 512 threads, 3 CTAs/SM.
// smem: Zh 20480 | Tb 34816 | Ab 8192 | sWd1 4096 | sWd2 2560
//       sbd1 128 | sbd2 128 | red 64   -> total 70464
// ---------------------------------------------------------------------------
__global__ void __launch_bounds__(NT, 3)
sample_kernel(const float* __restrict__ zmu,
              const float* __restrict__ Wd1, const float* __restrict__ bd1,
              const float* __restrict__ Wd2, const float* __restrict__ bd2,
              const float* __restrict__ X, const int* __restrict__ seedp)
{
    extern __shared__ char smraw[];
    __half* Zh = (__half*)(smraw);
    float* Tb   = (float*)(smraw + 20480);
    unsigned int* Ab = (unsigned int*)(smraw + 55296);
    float* sWd1 = (float*)(smraw + 63488);
    float* sWd2 = (float*)(smraw + 67584);
    float* sbd1 = (float*)(smraw + 70144);
    float* sbd2 = (float*)(smraw + 70272);
    float* red  = (float*)(smraw + 70400);

    __shared__ unsigned int sk[4];
    __shared__ int skg;

    const int t = threadIdx.x;
    const int lane = t & 31;
    const int w = t >> 5;
    const int bid = blockIdx.x;
    const int g  = bid & (Gc - 1);
    const int si = bid >> 6;

    unsigned int onev = 1u;
    asm("" : "+r"(onev));

    for (int e = t; e < Hc * Hc; e += NT) sWd1[e] = Wd1[e];
    for (int e = t; e < Hc * Fc; e += NT) sWd2[e] = Wd2[e];
    if (t < Hc) sbd1[t] = bd1[t];
    if (t < Fc) sbd2[t] = bd2[t];

    if (t == 0) {
        unsigned int seed = (unsigned int)(*seedp);
        U2 kf = threefry(0u, seed, 0u, (unsigned int)si, onev);
        U2 k1 = threefry(kf.x, kf.y, 0u, 0u, onev);
        U2 k2 = threefry(kf.x, kf.y, 0u, 1u, onev);
        U2 k3 = threefry(kf.x, kf.y, 0u, 2u, onev);
        sk[0] = k1.x; sk[1] = k1.y; sk[2] = k3.x; sk[3] = k3.y;

        const float tinyf = 1.17549435e-38f;
        float best = -1e30f; int kg = 0;
#pragma unroll
        for (int k = 0; k < Kc; ++k) {
            unsigned int b = rbits(k2.x, k2.y, (unsigned int)(g * Kc + k), onev);
            float f = bits_to_f01(b);
            float u = fmaxf(f, tinyf);
            float gv = -logf(-logf(u));
            float sc = g_la[g * Kc + k] + gv;
            if (sc > best) { best = sc; kg = k; }
        }
        skg = kg;
    }
    __syncthreads();

    const unsigned int k1x = sk[0], k1y = sk[1], k3x = sk[2], k3y = sk[3];
    const int ksel = skg;
    const float stdv = expf(-1.5f);

    // ---- sample Z = Z_mu + std*normal; store fp16 into smem ----
#pragma unroll 4
    for (int l = t; l < Nc * Hc; l += NT) {
        unsigned int b = rbits(k1x, k1y, (unsigned int)(g * (Nc * Hc) + l), onev);
        float f = bits_to_f01(b);
        float u = __fadd_rn(__fmul_rn(f, 2.0f), -0.99999994f);  // >= -c since f>=0
        float nv = 1.41421356f * erfinv32(u);
        int n = l >> 5, h = l & 31;
        float z = zmu[((size_t)g * Nc + n) * Hc + h] + stdv * nv;
        Zh[n * ZP + h] = __float2half(z);
    }

    // ---- sample adjacency: integer compare, two rows per warp iteration ----
    {
        const unsigned int* thr = g_uthr + ((size_t)ksel * Gc + g) * (Nc * Nc);
        const unsigned int cbase = (unsigned int)g * 65536u;
#pragma unroll
        for (int it = 0; it < 8; ++it) {
            const int iA = w + it * 32;
            const int iB = iA + 16;
            const int nwA = (iA + 31) >> 5;
            const int nwB = (iB + 31) >> 5;
            for (int wd = 0; wd < nwB; ++wd) {
                const int j = wd * 32 + lane;
                const bool doA = (wd < nwA);
                bool pA = false;
                if (doA) {
                    unsigned int bA = rbits(k3x, k3y, cbase + (unsigned int)(iA * Nc + j), onev);
                    pA = (j < iA) && ((bA >> 9) >= thr[iA * Nc + j]);
                }
                unsigned int bB = rbits(k3x, k3y, cbase + (unsigned int)(iB * Nc + j), onev);
                bool pB = (j < iB) && ((bB >> 9) >= thr[iB * Nc + j]);

                unsigned int wordA = __ballot_sync(0xffffffffu, pA);
                unsigned int wordB = __ballot_sync(0xffffffffu, pB);
                if (lane == 0) {
                    if (doA) Ab[iA * 8 + wd] = wordA;
                    Ab[iB * 8 + wd] = wordB;
                }
            }
            if (lane == 0) {
                for (int wd = nwA; wd < 8; ++wd) Ab[iA * 8 + wd] = 0u;
                for (int wd = nwB; wd < 8; ++wd) Ab[iB * 8 + wd] = 0u;
            }
        }
    }
    __syncthreads();

    // ---- symmetrize: Ab |= Ab^T via warp bit-transpose of 32x32 tiles ----
    {
        for (int task = w; task < 36; task += 16) {
            int ti = 0, basev = 0;
            while (basev + ti + 1 <= task) { basev += ti + 1; ti++; }
            int tj = task - basev;
            if (ti == tj) {
                unsigned int x = Ab[(ti * 32 + lane) * 8 + ti];
                unsigned int xt = bit_transpose32(x, lane);
                Ab[(ti * 32 + lane) * 8 + ti] = x | xt;
            } else {
                unsigned int x = Ab[(ti * 32 + lane) * 8 + tj];
                unsigned int xt = bit_transpose32(x, lane);
                Ab[(tj * 32 + lane) * 8 + ti] = xt;
            }
        }
    }
    __syncthreads();

    // ---- T1 = A @ Z ----
    amul_mma(smem_u32(Zh), Ab, Tb, t);
    __syncthreads();

    // ---- h = relu(T1 @ Wd1 + bd1) ----
    {
        const int r = t & 255;
        const int hb0 = (t >> 8) * 16;
        const float* tbr = Tb + r * TP;
#pragma unroll
        for (int half = 0; half < 2; ++half) {
            const int hbase = hb0 + half * 8;
            float acc[8];
#pragma unroll
            for (int hh = 0; hh < 8; ++hh) acc[hh] = sbd1[hbase + hh];
#pragma unroll 8
            for (int f = 0; f < Hc; ++f) {
                float tf = tbr[f];
#pragma unroll
                for (int hh = 0; hh < 8; ++hh)
                    acc[hh] = fmaf(tf, sWd1[f * Hc + hbase + hh], acc[hh]);
            }
#pragma unroll
            for (int hh = 0; hh < 8; ++hh)
                Zh[r * ZP + hbase + hh] = __float2half(fmaxf(acc[hh], 0.0f));
        }
    }
    __syncthreads();

    // ---- T2 = A @ h ----
    amul_mma(smem_u32(Zh), Ab, Tb, t);
    __syncthreads();

    // ---- Xmu = T2 @ Wd2 + bd2 ; squared error ----
    float local = 0.0f;
    {
        const int r = t & 255;
        const int fbase = (t >> 8) * 10;
        const float* tbr = Tb + r * TP;
        float acc[10];
#pragma unroll
        for (int ff = 0; ff < 10; ++ff) acc[ff] = sbd2[fbase + ff];
#pragma unroll 8
        for (int h = 0; h < Hc; ++h) {
            float th = tbr[h];
#pragma unroll
            for (int ff = 0; ff < 10; ++ff)
                acc[ff] = fmaf(th, sWd2[h * Fc + fbase + ff], acc[ff]);
        }
        const float* xr = X + ((size_t)g * Nc + r) * Fc + fbase;
#pragma unroll
        for (int ff = 0; ff < 10; ++ff) {
            float d = acc[ff] - xr[ff];
            local = fmaf(d, d, local);
        }
    }
#pragma unroll
    for (int s = 16; s > 0; s >>= 1)
        local += __shfl_xor_sync(0xffffffffu, local, s);
    if (lane == 0) red[w] = local;
    __syncthreads();
    if (t < 16) {
        float v = red[t];
#pragma unroll
        for (int s = 8; s > 0; s >>= 1)
            v += __shfl_xor_sync(0x0000ffffu, v, s);
        if (t == 0) g_partial[bid] = v;
    }
}

// ---------------------------------------------------------------------------
// Final loss reduction
// ---------------------------------------------------------------------------
__global__ void finalize_kernel(float* __restrict__ out)
{
    __shared__ double rd[256];
    int t = threadIdx.x;
    double s = 0.0;
    for (int i = t; i < NSc * Gc; i += 256) s += (double)g_partial[i];
    rd[t] = s;
    __syncthreads();
    for (int k = 128; k > 0; k >>= 1) {
        if (t < k) rd[t] += rd[t + k];
        __syncthreads();
    }
    if (t == 0) out[LOSS_OFF] = (float)(rd[0] * (0.5 / (double)(Gc * NSc)));
}

// ---------------------------------------------------------------------------
// Launch
// ---------------------------------------------------------------------------
extern "C" void kernel_launch(void* const* d_in, const int* in_sizes, int n_in,
                              void* d_out, int out_size)
{
    (void)in_sizes; (void)n_in; (void)out_size;
    const float* X      = (const float*)d_in[0];
    const float* Wz1    = (const float*)d_in[1];
    const float* bz1    = (const float*)d_in[2];
    const float* Wz2    = (const float*)d_in[3];
    const float* bz2    = (const float*)d_in[4];
    const float* Wa1    = (const float*)d_in[5];
    const float* ba1    = (const float*)d_in[6];
    const float* Wtheta = (const float*)d_in[7];
    const float* Walpha = (const float*)d_in[8];
    const float* balpha = (const float*)d_in[9];
    const float* Wd1    = (const float*)d_in[10];
    const float* bd1    = (const float*)d_in[11];
    const float* Wd2    = (const float*)d_in[12];
    const float* bd2    = (const float*)d_in[13];
    const int*   seed   = (const int*)d_in[14];

    float* out  = (float*)d_out;
    float* prob = out;
    float* la   = out + LA_OFF;
    float* zmu  = out + ZMU_OFF;

    cudaFuncSetAttribute(theta_kernel,  cudaFuncAttributeMaxDynamicSharedMemorySize, 46336);
    cudaFuncSetAttribute(sample_kernel, cudaFuncAttributeMaxDynamicSharedMemorySize, 70464);

    encode_kernel<<<Gc, 256>>>(X, Wz1, bz1, Wz2, bz2, Wa1, ba1,
                               Walpha, balpha, zmu, la);
    theta_kernel<<<Gc * Kc * 4, 256, 46336>>>(Wtheta, prob);
    sample_kernel<<<NSc * Gc, NT, 70464>>>(zmu, Wd1, bd1, Wd2, bd2, X, seed);
    finalize_kernel<<<1, 256>>>(out);
}

// round 15
// speedup vs baseline: 1.0556x; 1.0556x over previous
#include <cuda_runtime.h>
#include <cuda_fp16.h>
#include <stdint.h>

// ---------------------------------------------------------------------------
// Problem constants
// ---------------------------------------------------------------------------
#define Gc 64
#define Nc 256
#define Fc 20
#define Hc 32
#define Kc 5
#define NSc 100
#define ZP 40      // Z/h fp16 smem pitch (elements)
#define TP 34      // Tb fp32 smem pitch (elements)
#define NT 512

static const size_t PROB_ELEMS = (size_t)Gc * Nc * Nc * Kc;            // 20971520
static const size_t LA_OFF     = PROB_ELEMS;
static const size_t ZMU_OFF    = LA_OFF + (size_t)Gc * Kc;
static const size_t LOSS_OFF   = ZMU_OFF + (size_t)Gc * Nc * Hc;

// ---------------------------------------------------------------------------
// Scratch (device globals; no runtime allocation allowed)
// ---------------------------------------------------------------------------
__device__ float g_ha[(size_t)Gc * Nc * Hc];
__device__ float g_thresh[(size_t)Kc * Gc * Nc * Nc];   // sigmoid(-theta)
__device__ float g_la[Gc * Kc];
__device__ float g_partial[NSc * Gc];

// ---------------------------------------------------------------------------
// threefry2x32 (bit-exact JAX, partitionable mode); adds on FMA pipe via IMAD
// ---------------------------------------------------------------------------
struct U2 { unsigned int x, y; };

__device__ __forceinline__ unsigned int uadd_fma(unsigned int a, unsigned int b,
                                                 unsigned int one)
{
    unsigned int d;
    asm("mad.lo.u32 %0, %1, %2, %3;" : "=r"(d) : "r"(a), "r"(one), "r"(b));
    return d;
}

__device__ __forceinline__ unsigned int rotl32(unsigned int v, int r) {
    return (v << r) | (v >> (32 - r));
}

__device__ __forceinline__ U2 threefry(unsigned int k0, unsigned int k1,
                                       unsigned int x0, unsigned int x1,
                                       unsigned int onev)
{
    unsigned int k2 = k0 ^ k1 ^ 0x1BD11BDAu;
    x0 = uadd_fma(x0, k0, onev); x1 = uadd_fma(x1, k1, onev);
#define TFR(r) { x0 = uadd_fma(x0, x1, onev); x1 = rotl32(x1, r) ^ x0; }
    TFR(13) TFR(15) TFR(26) TFR(6)
    x0 = uadd_fma(x0, k1, onev); x1 = uadd_fma(x1, k2 + 1u, onev);
    TFR(17) TFR(29) TFR(16) TFR(24)
    x0 = uadd_fma(x0, k2, onev); x1 = uadd_fma(x1, k0 + 2u, onev);
    TFR(13) TFR(15) TFR(26) TFR(6)
    x0 = uadd_fma(x0, k0, onev); x1 = uadd_fma(x1, k1 + 3u, onev);
    TFR(17) TFR(29) TFR(16) TFR(24)
    x0 = uadd_fma(x0, k1, onev); x1 = uadd_fma(x1, k2 + 4u, onev);
    TFR(13) TFR(15) TFR(26) TFR(6)
    x0 = uadd_fma(x0, k2, onev); x1 = uadd_fma(x1, k0 + 5u, onev);
#undef TFR
    U2 r; r.x = x0; r.y = x1; return r;
}

__device__ __forceinline__ unsigned int rbits(unsigned int k0, unsigned int k1,
                                              unsigned int idx, unsigned int onev)
{
    U2 r = threefry(k0, k1, 0u, idx, onev);
    return r.x ^ r.y;
}

__device__ __forceinline__ float bits_to_f01(unsigned int b)
{
    return __uint_as_float((b >> 9) | 0x3f800000u) - 1.0f;
}

// XLA fp32 ErfInv (Giles polynomial); w via fast log
__device__ __forceinline__ float erfinv32(float x)
{
    float w = -__logf(1.0f - x * x);
    float p;
    if (w < 5.0f) {
        w = w - 2.5f;
        p = 2.81022636e-08f;
        p = fmaf(p, w, 3.43273939e-07f);
        p = fmaf(p, w, -3.5233877e-06f);
        p = fmaf(p, w, -4.39150654e-06f);
        p = fmaf(p, w, 0.00021858087f);
        p = fmaf(p, w, -0.00125372503f);
        p = fmaf(p, w, -0.00417768164f);
        p = fmaf(p, w, 0.246640727f);
        p = fmaf(p, w, 1.50140941f);
    } else {
        w = sqrtf(w) - 3.0f;
        p = -0.000200214257f;
        p = fmaf(p, w, 0.000100950558f);
        p = fmaf(p, w, 0.00134934322f);
        p = fmaf(p, w, -0.00367342844f);
        p = fmaf(p, w, 0.00573950773f);
        p = fmaf(p, w, -0.0076224613f);
        p = fmaf(p, w, 0.00943887047f);
        p = fmaf(p, w, 1.00167406f);
        p = fmaf(p, w, 2.83297682f);
    }
    return p * x;
}

__device__ __forceinline__ unsigned int smem_u32(const void* p)
{
    unsigned int a;
    asm("{ .reg .u64 t; cvta.to.shared.u64 t, %1; cvt.u32.u64 %0, t; }"
        : "=r"(a) : "l"(p));
    return a;
}

// 32x32 bit-matrix transpose, one row per lane (LSB = column 0).
__device__ __forceinline__ unsigned int bit_transpose32(unsigned int x, int lane)
{
#pragma unroll
    for (int j = 16; j >= 1; j >>= 1) {
        unsigned int mh = (j == 16) ? 0xFFFF0000u :
                          (j == 8)  ? 0xFF00FF00u :
                          (j == 4)  ? 0xF0F0F0F0u :
                          (j == 2)  ? 0xCCCCCCCCu : 0xAAAAAAAAu;
        unsigned int y = __shfl_xor_sync(0xffffffffu, x, j);
        if (lane & j) x = (x & mh) | ((y >> j) & ~mh);
        else          x = (x & ~mh) | ((y << j) & mh);
    }
    return x;
}

// ---------------------------------------------------------------------------
// Encoders: Z_mu, ha, and logit_alpha (fused)
// ---------------------------------------------------------------------------
__global__ void encode_kernel(const float* __restrict__ X,
                              const float* __restrict__ Wz1, const float* __restrict__ bz1,
                              const float* __restrict__ Wz2, const float* __restrict__ bz2,
                              const float* __restrict__ Wa1, const float* __restrict__ ba1,
                              const float* __restrict__ Walpha, const float* __restrict__ balpha,
                              float* __restrict__ zmu_out, float* __restrict__ la_out)
{
    __shared__ float sWz1[Fc * Hc], sbz1[Hc], sWz2[Hc * Hc], sbz2[Hc];
    __shared__ float sWa1[Fc * Hc], sba1[Hc];
    __shared__ float red[256];
    int t = threadIdx.x, g = blockIdx.x;
    for (int i = t; i < Fc * Hc; i += 256) { sWz1[i] = Wz1[i]; sWa1[i] = Wa1[i]; }
    for (int i = t; i < Hc * Hc; i += 256) sWz2[i] = Wz2[i];
    if (t < Hc) { sbz1[t] = bz1[t]; sbz2[t] = bz2[t]; sba1[t] = ba1[t]; }
    __syncthreads();

    float xr[Fc];
    const float* xp = X + ((size_t)g * Nc + t) * Fc;
#pragma unroll
    for (int f = 0; f < Fc; ++f) xr[f] = xp[f];

    float hz[Hc];
#pragma unroll
    for (int h = 0; h < Hc; ++h) {
        float a = sbz1[h];
#pragma unroll
        for (int f = 0; f < Fc; ++f) a = fmaf(xr[f], sWz1[f * Hc + h], a);
        hz[h] = fmaxf(a, 0.0f);
    }
    float* zo = zmu_out + ((size_t)g * Nc + t) * Hc;
#pragma unroll
    for (int h = 0; h < Hc; ++h) {
        float a = sbz2[h];
#pragma unroll
        for (int q = 0; q < Hc; ++q) a = fmaf(hz[q], sWz2[q * Hc + h], a);
        zo[h] = a;
    }
    float* hao = g_ha + ((size_t)g * Nc + t) * Hc;
#pragma unroll
    for (int h = 0; h < Hc; ++h) {
        float a = sba1[h];
#pragma unroll
        for (int f = 0; f < Fc; ++f) a = fmaf(xr[f], sWa1[f * Hc + h], a);
        hao[h] = fmaxf(a, 0.0f);
    }
    __syncthreads();

    int h = t & 31, grp = t >> 5;
    float s = 0.0f;
    for (int n = grp; n < Nc; n += 8) s += g_ha[((size_t)g * Nc + n) * Hc + h];
    red[t] = s;
    __syncthreads();
    if (grp == 0) {
        float m = red[h] + red[32 + h] + red[64 + h] + red[96 + h] +
                  red[128 + h] + red[160 + h] + red[192 + h] + red[224 + h];
        red[h] = m * (1.0f / (float)Nc);
    }
    __syncthreads();
    if (t < Kc) {
        float a = balpha[t];
#pragma unroll
        for (int hh = 0; hh < Hc; ++hh) a = fmaf(red[hh], Walpha[hh * Kc + t], a);
        la_out[g * Kc + t] = a;
        g_la[g * Kc + t] = a;
    }
}

// ---------------------------------------------------------------------------
// theta: prob_theta (output) + thresh = sigmoid(-logit) (scratch)  [R12 exact]
// ---------------------------------------------------------------------------
__global__ void theta_kernel(const float* __restrict__ Wtheta,
                             float* __restrict__ prob_out)
{
    extern __shared__ float sm[];
    float* ha = sm;                    // 256*33
    float* B  = sm + Nc * 33;          // 64*33
    float* Th = sm + Nc * 33 + 64 * 33;
    int bid = blockIdx.x;
    int g = bid / (Kc * 4);
    int rem = bid % (Kc * 4);
    int k = rem >> 2;
    int i0 = (rem & 3) * 64;
    int t = threadIdx.x;

    for (int e = t; e < Nc * Hc; e += 256) {
        int i = e >> 5, h = e & 31;
        ha[i * 33 + h] = g_ha[((size_t)g * Nc + i) * Hc + h];
    }
    for (int e = t; e < Hc * Hc; e += 256) Th[e] = Wtheta[(size_t)e * Kc + k];
    __syncthreads();

    for (int e = t; e < 64 * Hc; e += 256) {
        int i = e >> 5, f = e & 31;
        float a = 0.0f;
#pragma unroll
        for (int h = 0; h < Hc; ++h) a = fmaf(ha[(i0 + i) * 33 + h], Th[h * Hc + f], a);
        B[i * 33 + f] = a;
    }
    __syncthreads();

    int lane = t & 31, w = t >> 5;
    for (int ii = 0; ii < 8; ++ii) {
        int il = w * 8 + ii;
        int i  = i0 + il;
        float br[Hc];
#pragma unroll
        for (int f = 0; f < Hc; ++f) br[f] = B[il * 33 + f];
        for (int jh = 0; jh < 8; ++jh) {
            int j = jh * 32 + lane;
            float a = 0.0f;
#pragma unroll
            for (int f = 0; f < Hc; ++f) a = fmaf(br[f], ha[j * 33 + f], a);
            float e    = __expf(-a);
            float prob = __fdividef(1.0f, 1.0f + e);
            float th   = e * prob;
            prob_out[(((size_t)g * Nc + i) * Nc + j) * Kc + k] = (i == j) ? 0.0f : prob;
            g_thresh[(((size_t)k * Gc + g) * Nc + i) * Nc + j] = th;
        }
    }
}

// ---------------------------------------------------------------------------
// MMA helpers (base PTX ISA)
// ---------------------------------------------------------------------------
#define LDSM4T(r0, r1, r2, r3, addr)                                          \
    asm volatile("ldmatrix.sync.aligned.m8n8.x4.trans.shared.b16 "            \
                 "{%0,%1,%2,%3}, [%4];"                                       \
                 : "=r"(r0), "=r"(r1), "=r"(r2), "=r"(r3) : "r"(addr))

#define MMA16816F(d, a, b0_, b1_)                                             \
    asm volatile("mma.sync.aligned.m16n8k16.row.col.f32.f16.f16.f32 "         \
                 "{%0,%1,%2,%3}, {%4,%5,%6,%7}, {%8,%9}, {%0,%1,%2,%3};"      \
                 : "+f"((d)[0]), "+f"((d)[1]), "+f"((d)[2]), "+f"((d)[3])     \
                 : "r"((a)[0]), "r"((a)[1]), "r"((a)[2]), "r"((a)[3]),        \
                   "r"(b0_), "r"(b1_))

__device__ __forceinline__ unsigned int bits2h(unsigned int b)
{
    return (b & 1u) * 0x3C00u + ((b >> 1) & 1u) * 0x3C000000u;
}

__device__ __forceinline__ void amul_mma(unsigned int zh_b,
                                         const unsigned int* __restrict__ Ab,
                                         float* __restrict__ Tb, int t)
{
    const int l = t & 31, w = t >> 5;
    const int m0 = w * 16;
    const int g  = l >> 2;
    const int qs = (l & 3) * 2;
    const int krow = l & 15;
    const int kcol = (l >> 4) * 8;

    float acc[4][4];
#pragma unroll
    for (int nt = 0; nt < 4; ++nt)
#pragma unroll
        for (int r = 0; r < 4; ++r) acc[nt][r] = 0.0f;

#pragma unroll 4
    for (int kc = 0; kc < 16; ++kc) {
        const int sh = ((kc & 1) << 4) + qs;
        unsigned int a[4];
        {
            unsigned int wlo = Ab[(m0 + g) * 8 + (kc >> 1)];
            unsigned int whi = Ab[(m0 + 8 + g) * 8 + (kc >> 1)];
            unsigned int bl = wlo >> sh;
            unsigned int bh = whi >> sh;
            a[0] = bits2h(bl);
            a[1] = bits2h(bh);
            a[2] = bits2h(bl >> 8);
            a[3] = bits2h(bh >> 8);
        }
#pragma unroll
        for (int ng = 0; ng < 2; ++ng) {
            unsigned int off = (unsigned int)(((kc * 16 + krow) * ZP
                                               + ng * 16 + kcol) * 2);
            unsigned int h0, h1, h2, h3;
            LDSM4T(h0, h1, h2, h3, zh_b + off);
            MMA16816F(acc[ng * 2 + 0], a, h0, h1);
            MMA16816F(acc[ng * 2 + 1], a, h2, h3);
        }
    }

#pragma unroll
    for (int nt = 0; nt < 4; ++nt) {
        int r0 = m0 + g;
        int c  = nt * 8 + qs;
        *(float2*)&Tb[r0 * TP + c]       = make_float2(acc[nt][0], acc[nt][1]);
        *(float2*)&Tb[(r0 + 8) * TP + c] = make_float2(acc[nt][2], acc[nt][3]);
    }
}

// ---------------------------------------------------------------------------
// Fused per-(sample, graph) kernel, 512 threads, 3 CTAs/SM.
// smem: Zh 20480 | Tb 34816 | Ab 8192 | sWd1 4096 | sWd2 2560
//       sbd1 128 | sbd2 128 | red 64   -> total 70464
// ---------------------------------------------------------------------------
__global__ void __launch_bounds__(NT, 3)
sample_kernel(const float* __restrict__ zmu,
              const float* __restrict__ Wd1, const float* __restrict__ bd1,
              const float* __restrict__ Wd2, const float* __restrict__ bd2,
              const float* __restrict__ X, const int* __restrict__ seedp)
{
    extern __shared__ char smraw[];
    __half* Zh = (__half*)(smraw);
    float* Tb   = (float*)(smraw + 20480);
    unsigned int* Ab = (unsigned int*)(smraw + 55296);
    float* sWd1 = (float*)(smraw + 63488);
    float* sWd2 = (float*)(smraw + 67584);
    float* sbd1 = (float*)(smraw + 70144);
    float* sbd2 = (float*)(smraw + 70272);
    float* red  = (float*)(smraw + 70400);

    __shared__ unsigned int sk[4];
    __shared__ int skg;

    const int t = threadIdx.x;
    const int lane = t & 31;
    const int w = t >> 5;
    const int bid = blockIdx.x;
    const int g  = bid & (Gc - 1);
    const int si = bid >> 6;

    unsigned int onev = 1u;
    asm("" : "+r"(onev));

    for (int e = t; e < Hc * Hc; e += NT) sWd1[e] = Wd1[e];
    for (int e = t; e < Hc * Fc; e += NT) sWd2[e] = Wd2[e];
    if (t < Hc) sbd1[t] = bd1[t];
    if (t < Fc) sbd2[t] = bd2[t];

    if (t == 0) {
        unsigned int seed = (unsigned int)(*seedp);
        U2 kf = threefry(0u, seed, 0u, (unsigned int)si, onev);
        U2 k1 = threefry(kf.x, kf.y, 0u, 0u, onev);
        U2 k2 = threefry(kf.x, kf.y, 0u, 1u, onev);
        U2 k3 = threefry(kf.x, kf.y, 0u, 2u, onev);
        sk[0] = k1.x; sk[1] = k1.y; sk[2] = k3.x; sk[3] = k3.y;

        const float tinyf = 1.17549435e-38f;
        float best = -1e30f; int kg = 0;
#pragma unroll
        for (int k = 0; k < Kc; ++k) {
            unsigned int b = rbits(k2.x, k2.y, (unsigned int)(g * Kc + k), onev);
            float f = bits_to_f01(b);
            float u = fmaxf(f, tinyf);
            float gv = -logf(-logf(u));
            float sc = g_la[g * Kc + k] + gv;
            if (sc > best) { best = sc; kg = k; }
        }
        skg = kg;
    }
    __syncthreads();

    const unsigned int k1x = sk[0], k1y = sk[1], k3x = sk[2], k3y = sk[3];
    const int ksel = skg;
    const float stdv = expf(-1.5f);

    // ---- sample Z = Z_mu + std*normal; store fp16 into smem ----
#pragma unroll 4
    for (int l = t; l < Nc * Hc; l += NT) {
        unsigned int b = rbits(k1x, k1y, (unsigned int)(g * (Nc * Hc) + l), onev);
        float f = bits_to_f01(b);
        float u = __fadd_rn(__fmul_rn(f, 2.0f), -0.99999994f);
        u = fmaxf(-0.99999994f, u);
        float nv = 1.41421356f * erfinv32(u);
        int n = l >> 5, h = l & 31;
        float z = zmu[((size_t)g * Nc + n) * Hc + h] + stdv * nv;
        Zh[n * ZP + h] = __float2half(z);
    }

    // ---- sample adjacency: FOUR rows per warp iteration (ILP x4) ----
    {
        const float* thr = g_thresh + ((size_t)ksel * Gc + g) * (Nc * Nc);
        const float loA = 1e-6f;
        const float scA = (1.0f - 1e-6f) - 1e-6f;
        const unsigned int cbase = (unsigned int)g * 65536u;
#pragma unroll
        for (int it = 0; it < 4; ++it) {
            const int r0 = w + it * 64;
            const int r1 = r0 + 16;
            const int r2 = r0 + 32;
            const int r3 = r0 + 48;
            const int nw0 = (r0 + 31) >> 5;
            const int nw1 = (r1 + 31) >> 5;
            const int nw2 = (r2 + 31) >> 5;
            const int nw3 = (r3 + 31) >> 5;
            for (int wd = 0; wd < nw3; ++wd) {
                const int j = wd * 32 + lane;
                bool p0 = false, p1 = false, p2 = false;
                if (wd < nw0) {
                    unsigned int b0 = rbits(k3x, k3y, cbase + (unsigned int)(r0 * Nc + j), onev);
                    float u0 = fmaxf(loA, fmaf(bits_to_f01(b0), scA, loA));
                    p0 = (j < r0) && (u0 > thr[r0 * Nc + j]);
                }
                if (wd < nw1) {
                    unsigned int b1 = rbits(k3x, k3y, cbase + (unsigned int)(r1 * Nc + j), onev);
                    float u1 = fmaxf(loA, fmaf(bits_to_f01(b1), scA, loA));
                    p1 = (j < r1) && (u1 > thr[r1 * Nc + j]);
                }
                if (wd < nw2) {
                    unsigned int b2 = rbits(k3x, k3y, cbase + (unsigned int)(r2 * Nc + j), onev);
                    float u2 = fmaxf(loA, fmaf(bits_to_f01(b2), scA, loA));
                    p2 = (j < r2) && (u2 > thr[r2 * Nc + j]);
                }
                unsigned int b3 = rbits(k3x, k3y, cbase + (unsigned int)(r3 * Nc + j), onev);
                float u3 = fmaxf(loA, fmaf(bits_to_f01(b3), scA, loA));
                bool p3 = (j < r3) && (u3 > thr[r3 * Nc + j]);

                unsigned int w0 = __ballot_sync(0xffffffffu, p0);
                unsigned int w1 = __ballot_sync(0xffffffffu, p1);
                unsigned int w2 = __ballot_sync(0xffffffffu, p2);
                unsigned int w3 = __ballot_sync(0xffffffffu, p3);
                if (lane == 0) {
                    if (wd < nw0) Ab[r0 * 8 + wd] = w0;
                    if (wd < nw1) Ab[r1 * 8 + wd] = w1;
                    if (wd < nw2) Ab[r2 * 8 + wd] = w2;
                    Ab[r3 * 8 + wd] = w3;
                }
            }
            if (lane == 0) {
                for (int wd = nw0; wd < 8; ++wd) Ab[r0 * 8 + wd] = 0u;
                for (int wd = nw1; wd < 8; ++wd) Ab[r1 * 8 + wd] = 0u;
                for (int wd = nw2; wd < 8; ++wd) Ab[r2 * 8 + wd] = 0u;
                for (int wd = nw3; wd < 8; ++wd) Ab[r3 * 8 + wd] = 0u;
            }
        }
    }
    __syncthreads();

    // ---- symmetrize: Ab |= Ab^T via warp bit-transpose of 32x32 tiles ----
    {
        for (int task = w; task < 36; task += 16) {
            int ti = 0, basev = 0;
            while (basev + ti + 1 <= task) { basev += ti + 1; ti++; }
            int tj = task - basev;
            if (ti == tj) {
                unsigned int x = Ab[(ti * 32 + lane) * 8 + ti];
                unsigned int xt = bit_transpose32(x, lane);
                Ab[(ti * 32 + lane) * 8 + ti] = x | xt;
            } else {
                unsigned int x = Ab[(ti * 32 + lane) * 8 + tj];
                unsigned int xt = bit_transpose32(x, lane);
                Ab[(tj * 32 + lane) * 8 + ti] = xt;
            }
        }
    }
    __syncthreads();

    // ---- T1 = A @ Z ----
    amul_mma(smem_u32(Zh), Ab, Tb, t);
    __syncthreads();

    // ---- h = relu(T1 @ Wd1 + bd1) ----
    {
        const int r = t & 255;
        const int hb0 = (t >> 8) * 16;
        const float* tbr = Tb + r * TP;
#pragma unroll
        for (int half = 0; half < 2; ++half) {
            const int hbase = hb0 + half * 8;
            float acc[8];
#pragma unroll
            for (int hh = 0; hh < 8; ++hh) acc[hh] = sbd1[hbase + hh];
#pragma unroll 8
            for (int f = 0; f < Hc; ++f) {
                float tf = tbr[f];
#pragma unroll
                for (int hh = 0; hh < 8; ++hh)
                    acc[hh] = fmaf(tf, sWd1[f * Hc + hbase + hh], acc[hh]);
            }
#pragma unroll
            for (int hh = 0; hh < 8; ++hh)
                Zh[r * ZP + hbase + hh] = __float2half(fmaxf(acc[hh], 0.0f));
        }
    }
    __syncthreads();

    // ---- T2 = A @ h ----
    amul_mma(smem_u32(Zh), Ab, Tb, t);
    __syncthreads();

    // ---- Xmu = T2 @ Wd2 + bd2 ; squared error ----
    float local = 0.0f;
    {
        const int r = t & 255;
        const int fbase = (t >> 8) * 10;
        const float* tbr = Tb + r * TP;
        float acc[10];
#pragma unroll
        for (int ff = 0; ff < 10; ++ff) acc[ff] = sbd2[fbase + ff];
#pragma unroll 8
        for (int h = 0; h < Hc; ++h) {
            float th = tbr[h];
#pragma unroll
            for (int ff = 0; ff < 10; ++ff)
                acc[ff] = fmaf(th, sWd2[h * Fc + fbase + ff], acc[ff]);
        }
        const float* xr = X + ((size_t)g * Nc + r) * Fc + fbase;
#pragma unroll
        for (int ff = 0; ff < 10; ++ff) {
            float d = acc[ff] - xr[ff];
            local = fmaf(d, d, local);
        }
    }
#pragma unroll
    for (int s = 16; s > 0; s >>= 1)
        local += __shfl_xor_sync(0xffffffffu, local, s);
    if (lane == 0) red[w] = local;
    __syncthreads();
    if (t < 16) {
        float v = red[t];
#pragma unroll
        for (int s = 8; s > 0; s >>= 1)
            v += __shfl_xor_sync(0x0000ffffu, v, s);
        if (t == 0) g_partial[bid] = v;
    }
}

// ---------------------------------------------------------------------------
// Final loss reduction
// ---------------------------------------------------------------------------
__global__ void finalize_kernel(float* __restrict__ out)
{
    __shared__ double rd[256];
    int t = threadIdx.x;
    double s = 0.0;
    for (int i = t; i < NSc * Gc; i += 256) s += (double)g_partial[i];
    rd[t] = s;
    __syncthreads();
    for (int k = 128; k > 0; k >>= 1) {
        if (t < k) rd[t] += rd[t + k];
        __syncthreads();
    }
    if (t == 0) out[LOSS_OFF] = (float)(rd[0] * (0.5 / (double)(Gc * NSc)));
}

// ---------------------------------------------------------------------------
// Launch
// ---------------------------------------------------------------------------
extern "C" void kernel_launch(void* const* d_in, const int* in_sizes, int n_in,
                              void* d_out, int out_size)
{
    (void)in_sizes; (void)n_in; (void)out_size;
    const float* X      = (const float*)d_in[0];
    const float* Wz1    = (const float*)d_in[1];
    const float* bz1    = (const float*)d_in[2];
    const float* Wz2    = (const float*)d_in[3];
    const float* bz2    = (const float*)d_in[4];
    const float* Wa1    = (const float*)d_in[5];
    const float* ba1    = (const float*)d_in[6];
    const float* Wtheta = (const float*)d_in[7];
    const float* Walpha = (const float*)d_in[8];
    const float* balpha = (const float*)d_in[9];
    const float* Wd1    = (const float*)d_in[10];
    const float* bd1    = (const float*)d_in[11];
    const float* Wd2    = (const float*)d_in[12];
    const float* bd2    = (const float*)d_in[13];
    const int*   seed   = (const int*)d_in[14];

    float* out  = (float*)d_out;
    float* prob = out;
    float* la   = out + LA_OFF;
    float* zmu  = out + ZMU_OFF;

    cudaFuncSetAttribute(theta_kernel,  cudaFuncAttributeMaxDynamicSharedMemorySize, 46336);
    cudaFuncSetAttribute(sample_kernel, cudaFuncAttributeMaxDynamicSharedMemorySize, 70464);

    encode_kernel<<<Gc, 256>>>(X, Wz1, bz1, Wz2, bz2, Wa1, ba1,
                               Walpha, balpha, zmu, la);
    theta_kernel<<<Gc * Kc * 4, 256, 46336>>>(Wtheta, prob);
    sample_kernel<<<NSc * Gc, NT, 70464>>>(zmu, Wd1, bd1, Wd2, bd2, X, seed);
    finalize_kernel<<<1, 256>>>(out);
}

// round 16
// speedup vs baseline: 1.0635x; 1.0075x over previous
#include <cuda_runtime.h>
#include <cuda_fp16.h>
#include <stdint.h>

// ---------------------------------------------------------------------------
// Problem constants
// ---------------------------------------------------------------------------
#define Gc 64
#define Nc 256
#define Fc 20
#define Hc 32
#define Kc 5
#define NSc 100
#define ZP 40      // Z/h fp16 smem pitch (elements)
#define TP 34      // Tb fp32 smem pitch (elements)
#define NT 512

static const size_t PROB_ELEMS = (size_t)Gc * Nc * Nc * Kc;            // 20971520
static const size_t LA_OFF     = PROB_ELEMS;
static const size_t ZMU_OFF    = LA_OFF + (size_t)Gc * Kc;
static const size_t LOSS_OFF   = ZMU_OFF + (size_t)Gc * Nc * Hc;

// ---------------------------------------------------------------------------
// Scratch (device globals; no runtime allocation allowed)
// ---------------------------------------------------------------------------
__device__ float g_ha[(size_t)Gc * Nc * Hc];
__device__ float g_thresh[(size_t)Kc * Gc * Nc * Nc];   // sigmoid(-theta)
__device__ float g_la[Gc * Kc];
__device__ float g_partial[NSc * Gc];

// ---------------------------------------------------------------------------
// threefry2x32 (bit-exact JAX, partitionable mode); adds on FMA pipe via IMAD
// ---------------------------------------------------------------------------
struct U2 { unsigned int x, y; };

__device__ __forceinline__ unsigned int uadd_fma(unsigned int a, unsigned int b,
                                                 unsigned int one)
{
    unsigned int d;
    asm("mad.lo.u32 %0, %1, %2, %3;" : "=r"(d) : "r"(a), "r"(one), "r"(b));
    return d;
}

__device__ __forceinline__ unsigned int rotl32(unsigned int v, int r) {
    return (v << r) | (v >> (32 - r));
}

__device__ __forceinline__ U2 threefry(unsigned int k0, unsigned int k1,
                                       unsigned int x0, unsigned int x1,
                                       unsigned int onev)
{
    unsigned int k2 = k0 ^ k1 ^ 0x1BD11BDAu;
    x0 = uadd_fma(x0, k0, onev); x1 = uadd_fma(x1, k1, onev);
#define TFR(r) { x0 = uadd_fma(x0, x1, onev); x1 = rotl32(x1, r) ^ x0; }
    TFR(13) TFR(15) TFR(26) TFR(6)
    x0 = uadd_fma(x0, k1, onev); x1 = uadd_fma(x1, k2 + 1u, onev);
    TFR(17) TFR(29) TFR(16) TFR(24)
    x0 = uadd_fma(x0, k2, onev); x1 = uadd_fma(x1, k0 + 2u, onev);
    TFR(13) TFR(15) TFR(26) TFR(6)
    x0 = uadd_fma(x0, k0, onev); x1 = uadd_fma(x1, k1 + 3u, onev);
    TFR(17) TFR(29) TFR(16) TFR(24)
    x0 = uadd_fma(x0, k1, onev); x1 = uadd_fma(x1, k2 + 4u, onev);
    TFR(13) TFR(15) TFR(26) TFR(6)
    x0 = uadd_fma(x0, k2, onev); x1 = uadd_fma(x1, k0 + 5u, onev);
#undef TFR
    U2 r; r.x = x0; r.y = x1; return r;
}

__device__ __forceinline__ unsigned int rbits(unsigned int k0, unsigned int k1,
                                              unsigned int idx, unsigned int onev)
{
    U2 r = threefry(k0, k1, 0u, idx, onev);
    return r.x ^ r.y;
}

__device__ __forceinline__ float bits_to_f01(unsigned int b)
{
    return __uint_as_float((b >> 9) | 0x3f800000u) - 1.0f;
}

// XLA fp32 ErfInv (Giles polynomial); w via fast log
__device__ __forceinline__ float erfinv32(float x)
{
    float w = -__logf(1.0f - x * x);
    float p;
    if (w < 5.0f) {
        w = w - 2.5f;
        p = 2.81022636e-08f;
        p = fmaf(p, w, 3.43273939e-07f);
        p = fmaf(p, w, -3.5233877e-06f);
        p = fmaf(p, w, -4.39150654e-06f);
        p = fmaf(p, w, 0.00021858087f);
        p = fmaf(p, w, -0.00125372503f);
        p = fmaf(p, w, -0.00417768164f);
        p = fmaf(p, w, 0.246640727f);
        p = fmaf(p, w, 1.50140941f);
    } else {
        w = sqrtf(w) - 3.0f;
        p = -0.000200214257f;
        p = fmaf(p, w, 0.000100950558f);
        p = fmaf(p, w, 0.00134934322f);
        p = fmaf(p, w, -0.00367342844f);
        p = fmaf(p, w, 0.00573950773f);
        p = fmaf(p, w, -0.0076224613f);
        p = fmaf(p, w, 0.00943887047f);
        p = fmaf(p, w, 1.00167406f);
        p = fmaf(p, w, 2.83297682f);
    }
    return p * x;
}

__device__ __forceinline__ unsigned int smem_u32(const void* p)
{
    unsigned int a;
    asm("{ .reg .u64 t; cvta.to.shared.u64 t, %1; cvt.u32.u64 %0, t; }"
        : "=r"(a) : "l"(p));
    return a;
}

// 32x32 bit-matrix transpose, one row per lane (LSB = column 0).
__device__ __forceinline__ unsigned int bit_transpose32(unsigned int x, int lane)
{
#pragma unroll
    for (int j = 16; j >= 1; j >>= 1) {
        unsigned int mh = (j == 16) ? 0xFFFF0000u :
                          (j == 8)  ? 0xFF00FF00u :
                          (j == 4)  ? 0xF0F0F0F0u :
                          (j == 2)  ? 0xCCCCCCCCu : 0xAAAAAAAAu;
        unsigned int y = __shfl_xor_sync(0xffffffffu, x, j);
        if (lane & j) x = (x & mh) | ((y >> j) & ~mh);
        else          x = (x & ~mh) | ((y << j) & mh);
    }
    return x;
}

// ---------------------------------------------------------------------------
// Encoders: Z_mu, ha, and logit_alpha (fused)
// ---------------------------------------------------------------------------
__global__ void encode_kernel(const float* __restrict__ X,
                              const float* __restrict__ Wz1, const float* __restrict__ bz1,
                              const float* __restrict__ Wz2, const float* __restrict__ bz2,
                              const float* __restrict__ Wa1, const float* __restrict__ ba1,
                              const float* __restrict__ Walpha, const float* __restrict__ balpha,
                              float* __restrict__ zmu_out, float* __restrict__ la_out)
{
    __shared__ float sWz1[Fc * Hc], sbz1[Hc], sWz2[Hc * Hc], sbz2[Hc];
    __shared__ float sWa1[Fc * Hc], sba1[Hc];
    __shared__ float red[256];
    int t = threadIdx.x, g = blockIdx.x;
    for (int i = t; i < Fc * Hc; i += 256) { sWz1[i] = Wz1[i]; sWa1[i] = Wa1[i]; }
    for (int i = t; i < Hc * Hc; i += 256) sWz2[i] = Wz2[i];
    if (t < Hc) { sbz1[t] = bz1[t]; sbz2[t] = bz2[t]; sba1[t] = ba1[t]; }
    __syncthreads();

    float xr[Fc];
    const float* xp = X + ((size_t)g * Nc + t) * Fc;
#pragma unroll
    for (int f = 0; f < Fc; ++f) xr[f] = xp[f];

    float hz[Hc];
#pragma unroll
    for (int h = 0; h < Hc; ++h) {
        float a = sbz1[h];
#pragma unroll
        for (int f = 0; f < Fc; ++f) a = fmaf(xr[f], sWz1[f * Hc + h], a);
        hz[h] = fmaxf(a, 0.0f);
    }
    float* zo = zmu_out + ((size_t)g * Nc + t) * Hc;
#pragma unroll
    for (int h = 0; h < Hc; ++h) {
        float a = sbz2[h];
#pragma unroll
        for (int q = 0; q < Hc; ++q) a = fmaf(hz[q], sWz2[q * Hc + h], a);
        zo[h] = a;
    }
    float* hao = g_ha + ((size_t)g * Nc + t) * Hc;
#pragma unroll
    for (int h = 0; h < Hc; ++h) {
        float a = sba1[h];
#pragma unroll
        for (int f = 0; f < Fc; ++f) a = fmaf(xr[f], sWa1[f * Hc + h], a);
        hao[h] = fmaxf(a, 0.0f);
    }
    __syncthreads();

    int h = t & 31, grp = t >> 5;
    float s = 0.0f;
    for (int n = grp; n < Nc; n += 8) s += g_ha[((size_t)g * Nc + n) * Hc + h];
    red[t] = s;
    __syncthreads();
    if (grp == 0) {
        float m = red[h] + red[32 + h] + red[64 + h] + red[96 + h] +
                  red[128 + h] + red[160 + h] + red[192 + h] + red[224 + h];
        red[h] = m * (1.0f / (float)Nc);
    }
    __syncthreads();
    if (t < Kc) {
        float a = balpha[t];
#pragma unroll
        for (int hh = 0; hh < Hc; ++hh) a = fmaf(red[hh], Walpha[hh * Kc + t], a);
        la_out[g * Kc + t] = a;
        g_la[g * Kc + t] = a;
    }
}

// ---------------------------------------------------------------------------
// theta: prob_theta (output) + thresh = sigmoid(-logit) (scratch)
// ---------------------------------------------------------------------------
__global__ void theta_kernel(const float* __restrict__ Wtheta,
                             float* __restrict__ prob_out)
{
    extern __shared__ float sm[];
    float* ha = sm;                    // 256*33
    float* B  = sm + Nc * 33;          // 64*33
    float* Th = sm + Nc * 33 + 64 * 33;
    int bid = blockIdx.x;
    int g = bid / (Kc * 4);
    int rem = bid % (Kc * 4);
    int k = rem >> 2;
    int i0 = (rem & 3) * 64;
    int t = threadIdx.x;

    for (int e = t; e < Nc * Hc; e += 256) {
        int i = e >> 5, h = e & 31;
        ha[i * 33 + h] = g_ha[((size_t)g * Nc + i) * Hc + h];
    }
    for (int e = t; e < Hc * Hc; e += 256) Th[e] = Wtheta[(size_t)e * Kc + k];
    __syncthreads();

    for (int e = t; e < 64 * Hc; e += 256) {
        int i = e >> 5, f = e & 31;
        float a = 0.0f;
#pragma unroll
        for (int h = 0; h < Hc; ++h) a = fmaf(ha[(i0 + i) * 33 + h], Th[h * Hc + f], a);
        B[i * 33 + f] = a;
    }
    __syncthreads();

    int lane = t & 31, w = t >> 5;
    for (int ii = 0; ii < 8; ++ii) {
        int il = w * 8 + ii;
        int i  = i0 + il;
        float br[Hc];
#pragma unroll
        for (int f = 0; f < Hc; ++f) br[f] = B[il * 33 + f];
        for (int jh = 0; jh < 8; ++jh) {
            int j = jh * 32 + lane;
            float a = 0.0f;
#pragma unroll
            for (int f = 0; f < Hc; ++f) a = fmaf(br[f], ha[j * 33 + f], a);
            float e    = __expf(-a);
            float prob = __fdividef(1.0f, 1.0f + e);
            float th   = e * prob;
            prob_out[(((size_t)g * Nc + i) * Nc + j) * Kc + k] = (i == j) ? 0.0f : prob;
            g_thresh[(((size_t)k * Gc + g) * Nc + i) * Nc + j] = th;
        }
    }
}

// ---------------------------------------------------------------------------
// MMA helpers (base PTX ISA)
// ---------------------------------------------------------------------------
#define LDSM4T(r0, r1, r2, r3, addr)                                          \
    asm volatile("ldmatrix.sync.aligned.m8n8.x4.trans.shared.b16 "            \
                 "{%0,%1,%2,%3}, [%4];"                                       \
                 : "=r"(r0), "=r"(r1), "=r"(r2), "=r"(r3) : "r"(addr))

#define MMA16816F(d, a, b0_, b1_)                                             \
    asm volatile("mma.sync.aligned.m16n8k16.row.col.f32.f16.f16.f32 "         \
                 "{%0,%1,%2,%3}, {%4,%5,%6,%7}, {%8,%9}, {%0,%1,%2,%3};"      \
                 : "+f"((d)[0]), "+f"((d)[1]), "+f"((d)[2]), "+f"((d)[3])     \
                 : "r"((a)[0]), "r"((a)[1]), "r"((a)[2]), "r"((a)[3]),        \
                   "r"(b0_), "r"(b1_))

__device__ __forceinline__ unsigned int bits2h(unsigned int b)
{
    return (b & 1u) * 0x3C00u + ((b >> 1) & 1u) * 0x3C000000u;
}

__device__ __forceinline__ void amul_mma(unsigned int zh_b,
                                         const unsigned int* __restrict__ Ab,
                                         float* __restrict__ Tb, int t)
{
    const int l = t & 31, w = t >> 5;
    const int m0 = w * 16;
    const int g  = l >> 2;
    const int qs = (l & 3) * 2;
    const int krow = l & 15;
    const int kcol = (l >> 4) * 8;

    float acc[4][4];
#pragma unroll
    for (int nt = 0; nt < 4; ++nt)
#pragma unroll
        for (int r = 0; r < 4; ++r) acc[nt][r] = 0.0f;

#pragma unroll 4
    for (int kc = 0; kc < 16; ++kc) {
        const int sh = ((kc & 1) << 4) + qs;
        unsigned int a[4];
        {
            unsigned int wlo = Ab[(m0 + g) * 8 + (kc >> 1)];
            unsigned int whi = Ab[(m0 + 8 + g) * 8 + (kc >> 1)];
            unsigned int bl = wlo >> sh;
            unsigned int bh = whi >> sh;
            a[0] = bits2h(bl);
            a[1] = bits2h(bh);
            a[2] = bits2h(bl >> 8);
            a[3] = bits2h(bh >> 8);
        }
#pragma unroll
        for (int ng = 0; ng < 2; ++ng) {
            unsigned int off = (unsigned int)(((kc * 16 + krow) * ZP
                                               + ng * 16 + kcol) * 2);
            unsigned int h0, h1, h2, h3;
            LDSM4T(h0, h1, h2, h3, zh_b + off);
            MMA16816F(acc[ng * 2 + 0], a, h0, h1);
            MMA16816F(acc[ng * 2 + 1], a, h2, h3);
        }
    }

#pragma unroll
    for (int nt = 0; nt < 4; ++nt) {
        int r0 = m0 + g;
        int c  = nt * 8 + qs;
        *(float2*)&Tb[r0 * TP + c]       = make_float2(acc[nt][0], acc[nt][1]);
        *(float2*)&Tb[(r0 + 8) * TP + c] = make_float2(acc[nt][2], acc[nt][3]);
    }
}

// ---------------------------------------------------------------------------
// Fused per-(sample, graph) kernel, 512 threads, 3 CTAs/SM.
// smem: Zh 20480 | Tb 34816 | Ab 8192 | sWd1 4096 | sWd2 2560
//       sbd1 128 | sbd2 128 | red 64   -> total 70464
// ---------------------------------------------------------------------------
__global__ void __launch_bounds__(NT, 3)
sample_kernel(const float* __restrict__ zmu,
              const float* __restrict__ Wd1, const float* __restrict__ bd1,
              const float* __restrict__ Wd2, const float* __restrict__ bd2,
              const float* __restrict__ X, const int* __restrict__ seedp)
{
    extern __shared__ char smraw[];
    __half* Zh = (__half*)(smraw);
    float* Tb   = (float*)(smraw + 20480);
    unsigned int* Ab = (unsigned int*)(smraw + 55296);
    float* sWd1 = (float*)(smraw + 63488);
    float* sWd2 = (float*)(smraw + 67584);
    float* sbd1 = (float*)(smraw + 70144);
    float* sbd2 = (float*)(smraw + 70272);
    float* red  = (float*)(smraw + 70400);

    __shared__ unsigned int sk[4];
    __shared__ int skg;

    const int t = threadIdx.x;
    const int lane = t & 31;
    const int w = t >> 5;
    const int bid = blockIdx.x;
    const int g  = bid & (Gc - 1);
    const int si = bid >> 6;

    unsigned int onev = 1u;
    asm("" : "+r"(onev));

    for (int e = t; e < Hc * Hc; e += NT) sWd1[e] = Wd1[e];
    for (int e = t; e < Hc * Fc; e += NT) sWd2[e] = Wd2[e];
    if (t < Hc) sbd1[t] = bd1[t];
    if (t < Fc) sbd2[t] = bd2[t];

    if (t == 0) {
        unsigned int seed = (unsigned int)(*seedp);
        U2 kf = threefry(0u, seed, 0u, (unsigned int)si, onev);
        U2 k1 = threefry(kf.x, kf.y, 0u, 0u, onev);
        U2 k2 = threefry(kf.x, kf.y, 0u, 1u, onev);
        U2 k3 = threefry(kf.x, kf.y, 0u, 2u, onev);
        sk[0] = k1.x; sk[1] = k1.y; sk[2] = k3.x; sk[3] = k3.y;

        const float tinyf = 1.17549435e-38f;
        float best = -1e30f; int kg = 0;
#pragma unroll
        for (int k = 0; k < Kc; ++k) {
            unsigned int b = rbits(k2.x, k2.y, (unsigned int)(g * Kc + k), onev);
            float f = bits_to_f01(b);
            float u = fmaxf(f, tinyf);
            float gv = -logf(-logf(u));
            float sc = g_la[g * Kc + k] + gv;
            if (sc > best) { best = sc; kg = k; }
        }
        skg = kg;
    }
    __syncthreads();

    const unsigned int k1x = sk[0], k1y = sk[1], k3x = sk[2], k3y = sk[3];
    const int ksel = skg;
    const float stdv = expf(-1.5f);

    // ---- sample Z = Z_mu + std*normal; store fp16 into smem ----
    // (clamp vs -0.99999994 is provably redundant: f>=0 and -c representable)
#pragma unroll 4
    for (int l = t; l < Nc * Hc; l += NT) {
        unsigned int b = rbits(k1x, k1y, (unsigned int)(g * (Nc * Hc) + l), onev);
        float f = bits_to_f01(b);
        float u = __fadd_rn(__fmul_rn(f, 2.0f), -0.99999994f);
        float nv = 1.41421356f * erfinv32(u);
        int n = l >> 5, h = l & 31;
        float z = zmu[((size_t)g * Nc + n) * Hc + h] + stdv * nv;
        Zh[n * ZP + h] = __float2half(z);
    }

    // ---- sample adjacency: two rows per warp iteration (ILP pairing) ----
    {
        const float* thr = g_thresh + ((size_t)ksel * Gc + g) * (Nc * Nc);
        const float loA = 1e-6f;
        const float scA = (1.0f - 1e-6f) - 1e-6f;
        const unsigned int cbase = (unsigned int)g * 65536u;
#pragma unroll
        for (int it = 0; it < 8; ++it) {
            const int iA = w + it * 32;
            const int iB = iA + 16;
            const int nwA = (iA + 31) >> 5;
            const int nwB = (iB + 31) >> 5;
            for (int wd = 0; wd < nwB; ++wd) {
                const int j = wd * 32 + lane;
                const bool doA = (wd < nwA);
                bool pA = false;
                if (doA) {
                    unsigned int bA = rbits(k3x, k3y, cbase + (unsigned int)(iA * Nc + j), onev);
                    float uA = fmaxf(loA, fmaf(bits_to_f01(bA), scA, loA));
                    pA = (j < iA) && (uA > thr[iA * Nc + j]);
                }
                unsigned int bB = rbits(k3x, k3y, cbase + (unsigned int)(iB * Nc + j), onev);
                float uB = fmaxf(loA, fmaf(bits_to_f01(bB), scA, loA));
                bool pB = (j < iB) && (uB > thr[iB * Nc + j]);

                unsigned int wordA = __ballot_sync(0xffffffffu, pA);
                unsigned int wordB = __ballot_sync(0xffffffffu, pB);
                if (lane == 0) {
                    if (doA) Ab[iA * 8 + wd] = wordA;
                    Ab[iB * 8 + wd] = wordB;
                }
            }
            if (lane == 0) {
                for (int wd = nwA; wd < 8; ++wd) Ab[iA * 8 + wd] = 0u;
                for (int wd = nwB; wd < 8; ++wd) Ab[iB * 8 + wd] = 0u;
            }
        }
    }
    __syncthreads();

    // ---- symmetrize: Ab |= Ab^T via warp bit-transpose of 32x32 tiles ----
    {
        for (int task = w; task < 36; task += 16) {
            int ti = 0, basev = 0;
            while (basev + ti + 1 <= task) { basev += ti + 1; ti++; }
            int tj = task - basev;
            if (ti == tj) {
                unsigned int x = Ab[(ti * 32 + lane) * 8 + ti];
                unsigned int xt = bit_transpose32(x, lane);
                Ab[(ti * 32 + lane) * 8 + ti] = x | xt;
            } else {
                unsigned int x = Ab[(ti * 32 + lane) * 8 + tj];
                unsigned int xt = bit_transpose32(x, lane);
                Ab[(tj * 32 + lane) * 8 + ti] = xt;
            }
        }
    }
    __syncthreads();

    // ---- T1 = A @ Z ----
    amul_mma(smem_u32(Zh), Ab, Tb, t);
    __syncthreads();

    // ---- h = relu(T1 @ Wd1 + bd1) ----
    {
        const int r = t & 255;
        const int hb0 = (t >> 8) * 16;
        const float* tbr = Tb + r * TP;
#pragma unroll
        for (int half = 0; half < 2; ++half) {
            const int hbase = hb0 + half * 8;
            float acc[8];
#pragma unroll
            for (int hh = 0; hh < 8; ++hh) acc[hh] = sbd1[hbase + hh];
#pragma unroll 8
            for (int f = 0; f < Hc; ++f) {
                float tf = tbr[f];
#pragma unroll
                for (int hh = 0; hh < 8; ++hh)
                    acc[hh] = fmaf(tf, sWd1[f * Hc + hbase + hh], acc[hh]);
            }
#pragma unroll
            for (int hh = 0; hh < 8; ++hh)
                Zh[r * ZP + hbase + hh] = __float2half(fmaxf(acc[hh], 0.0f));
        }
    }
    __syncthreads();

    // ---- T2 = A @ h ----
    amul_mma(smem_u32(Zh), Ab, Tb, t);
    __syncthreads();

    // ---- Xmu = T2 @ Wd2 + bd2 ; squared error ----
    float local = 0.0f;
    {
        const int r = t & 255;
        const int fbase = (t >> 8) * 10;
        const float* tbr = Tb + r * TP;
        float acc[10];
#pragma unroll
        for (int ff = 0; ff < 10; ++ff) acc[ff] = sbd2[fbase + ff];
#pragma unroll 8
        for (int h = 0; h < Hc; ++h) {
            float th = tbr[h];
#pragma unroll
            for (int ff = 0; ff < 10; ++ff)
                acc[ff] = fmaf(th, sWd2[h * Fc + fbase + ff], acc[ff]);
        }
        const float* xr = X + ((size_t)g * Nc + r) * Fc + fbase;
#pragma unroll
        for (int ff = 0; ff < 10; ++ff) {
            float d = acc[ff] - xr[ff];
            local = fmaf(d, d, local);
        }
    }
#pragma unroll
    for (int s = 16; s > 0; s >>= 1)
        local += __shfl_xor_sync(0xffffffffu, local, s);
    if (lane == 0) red[w] = local;
    __syncthreads();
    if (t < 16) {
        float v = red[t];
#pragma unroll
        for (int s = 8; s > 0; s >>= 1)
            v += __shfl_xor_sync(0x0000ffffu, v, s);
        if (t == 0) g_partial[bid] = v;
    }
}

// ---------------------------------------------------------------------------
// Final loss reduction
// ---------------------------------------------------------------------------
__global__ void finalize_kernel(float* __restrict__ out)
{
    __shared__ double rd[256];
    int t = threadIdx.x;
    double s = 0.0;
    for (int i = t; i < NSc * Gc; i += 256) s += (double)g_partial[i];
    rd[t] = s;
    __syncthreads();
    for (int k = 128; k > 0; k >>= 1) {
        if (t < k) rd[t] += rd[t + k];
        __syncthreads();
    }
    if (t == 0) out[LOSS_OFF] = (float)(rd[0] * (0.5 / (double)(Gc * NSc)));
}

// ---------------------------------------------------------------------------
// Launch
// ---------------------------------------------------------------------------
extern "C" void kernel_launch(void* const* d_in, const int* in_sizes, int n_in,
                              void* d_out, int out_size)
{
    (void)in_sizes; (void)n_in; (void)out_size;
    const float* X      = (const float*)d_in[0];
    const float* Wz1    = (const float*)d_in[1];
    const float* bz1    = (const float*)d_in[2];
    const float* Wz2    = (const float*)d_in[3];
    const float* bz2    = (const float*)d_in[4];
    const float* Wa1    = (const float*)d_in[5];
    const float* ba1    = (const float*)d_in[6];
    const float* Wtheta = (const float*)d_in[7];
    const float* Walpha = (const float*)d_in[8];
    const float* balpha = (const float*)d_in[9];
    const float* Wd1    = (const float*)d_in[10];
    const float* bd1    = (const float*)d_in[11];
    const float* Wd2    = (const float*)d_in[12];
    const float* bd2    = (const float*)d_in[13];
    const int*   seed   = (const int*)d_in[14];

    float* out  = (float*)d_out;
    float* prob = out;
    float* la   = out + LA_OFF;
    float* zmu  = out + ZMU_OFF;

    cudaFuncSetAttribute(theta_kernel,  cudaFuncAttributeMaxDynamicSharedMemorySize, 46336);
    cudaFuncSetAttribute(sample_kernel, cudaFuncAttributeMaxDynamicSharedMemorySize, 70464);

    encode_kernel<<<Gc, 256>>>(X, Wz1, bz1, Wz2, bz2, Wa1, ba1,
                               Walpha, balpha, zmu, la);
    theta_kernel<<<Gc * Kc * 4, 256, 46336>>>(Wtheta, prob);
    sample_kernel<<<NSc * Gc, NT, 70464>>>(zmu, Wd1, bd1, Wd2, bd2, X, seed);
    finalize_kernel<<<1, 256>>>(out);
}